// round 12
// baseline (speedup 1.0000x reference)
#include <cuda_runtime.h>
#include <cuda_fp16.h>
#include <cstdint>

// ---------------------------------------------------------------------------
// GroupedLinear: y[b, g*256+o] = sum_i x[b, g*256+i] * W[g,o,i] + bias[g,o]
// 16 independent GEMMs: M=8192, N=256, K=256, fp32 in/out.
//
// R11: 82.4us total, main 78us, tensor 36%, L1 77% -> L1tex wavefronts bind:
// scattered epilogue STG (4096 wv/tile) + sector-wasteful A-LDG (8 wv/instr).
// R12: sector-perfect A-LDG (4 rows x 128B per warp instr) + smem-staged
// epilogue (coalesced STG.128). Core (fused cvt GEMM, persistent 152 CTAs,
// 3-stage, mma.m16n8k16.f16, W-fp16 prepass) unchanged.
// ---------------------------------------------------------------------------

namespace gl {

constexpr int INF  = 4096;
constexpr int NG   = 16;
constexpr int GIN  = 256;          // K per group
constexpr int GOUT = 256;          // N per group
constexpr int MT   = 128;          // CTA M tile
constexpr int NT   = 256;          // CTA N tile (full group)
constexpr int KCH  = 64;           // K chunk: 64 halves = 128 B rows
constexpr int NCHUNK = 4;          // K chunks per tile (256/64)
constexpr int TILES = 1024;        // 16 groups x 64 m-tiles
constexpr int NCTA  = 152;         // 1 CTA per SM (GB300: 152 SMs)
constexpr int NTHREADS = 256;      // 8 warps, 2(M) x 4(N), warp tile 64x64

constexpr int A_BYTES = MT * KCH * 2;           // 16 KB per stage
constexpr int B_BYTES = NT * KCH * 2;           // 32 KB per stage
constexpr int STAGE_BYTES = A_BYTES + B_BYTES;  // 48 KB

constexpr int OFF_STAGE = 1024;
constexpr int OFF_EPI   = OFF_STAGE + 3 * STAGE_BYTES;   // epilogue staging
constexpr int EPI_STRIDE_B = 1040;                       // 260 floats, 16B-aligned
constexpr int EPI_BYTES = 64 * EPI_STRIDE_B;             // 66560 B
constexpr int SMEM_TOTAL = OFF_EPI + EPI_BYTES;          // 215040 B -> 1 CTA/SM

__device__ __forceinline__ uint32_t swz(uint32_t x) {
    return x ^ ((x >> 3) & 0x70);
}

__device__ __forceinline__ void cp16(uint32_t dst, const void* src) {
    asm volatile("cp.async.cg.shared.global [%0], [%1], 16;"
                 :: "r"(dst), "l"(src) : "memory");
}

__device__ __forceinline__ uint32_t smem_u32(const void* p) {
    uint32_t a;
    asm("{ .reg .u64 t; cvta.to.shared.u64 t, %1; cvt.u32.u64 %0, t; }"
        : "=r"(a) : "l"(p));
    return a;
}

__device__ __forceinline__ void ldsm4(uint32_t& r0, uint32_t& r1,
                                      uint32_t& r2, uint32_t& r3,
                                      uint32_t addr) {
    asm volatile("ldmatrix.sync.aligned.m8n8.x4.shared.b16 {%0,%1,%2,%3}, [%4];"
                 : "=r"(r0), "=r"(r1), "=r"(r2), "=r"(r3) : "r"(addr));
}

__device__ __forceinline__ void mma_f16(float* c,
                                        uint32_t a0, uint32_t a1,
                                        uint32_t a2, uint32_t a3,
                                        uint32_t b0, uint32_t b1) {
    asm volatile(
        "mma.sync.aligned.m16n8k16.row.col.f32.f16.f16.f32 "
        "{%0,%1,%2,%3}, {%4,%5,%6,%7}, {%8,%9}, {%0,%1,%2,%3};"
        : "+f"(c[0]), "+f"(c[1]), "+f"(c[2]), "+f"(c[3])
        : "r"(a0), "r"(a1), "r"(a2), "r"(a3), "r"(b0), "r"(b1));
}

__device__ __forceinline__ uint32_t h2u(__half2 h) {
    return *reinterpret_cast<uint32_t*>(&h);
}

} // namespace gl

using namespace gl;

// fp16 copy of W (2MB), produced once per launch (idempotent, deterministic).
__device__ __half g_Wh[NG * GOUT * GIN];

__global__ __launch_bounds__(256, 8)
void GroupedLinear_cvtW_kernel(const float4* __restrict__ in,
                               uint2* __restrict__ out, int n4) {
    const int stride = gridDim.x * 256;
    for (int i = blockIdx.x * 256 + threadIdx.x; i < n4; i += stride) {
        float4 v = in[i];
        __half2 lo = __floats2half2_rn(v.x, v.y);
        __half2 hi = __floats2half2_rn(v.z, v.w);
        uint2 o;
        o.x = *reinterpret_cast<uint32_t*>(&lo);
        o.y = *reinterpret_cast<uint32_t*>(&hi);
        out[i] = o;
    }
}

__global__ __launch_bounds__(NTHREADS, 1)
void GroupedLinear_35364760715975_kernel(const float* __restrict__ x,
                                         const float* __restrict__ bias,
                                         float* __restrict__ y)
{
    extern __shared__ char smem[];
    const uint32_t sbase = smem_u32(smem);
    const int tid = threadIdx.x;
    const int bid = blockIdx.x;

    // ---- shared loader lane geometry: 4 rows x 128B per warp instr ----
    const int lrr = tid >> 3;        // row 0..31
    const int lss = tid & 7;         // 16B slot within 128B fp16 row

    // B loader (cp.async from g_Wh): 8 iters x 32 rows = 256 rows
    uint32_t dstoB[8];
    #pragma unroll
    for (int i = 0; i < 8; i++)
        dstoB[i] = swz((uint32_t)((lrr + i * 32) * 128 + lss * 16));

    auto loadB = [&](int q, int buf) {
        const int t  = q >> 2;
        const int kc = q & 3;
        const int g  = (bid + t * NCTA) >> 6;
        const __half* ws = g_Wh + (size_t)g * GOUT * GIN
                                + (size_t)lrr * GIN + kc * KCH + lss * 8;
        const uint32_t bbase = sbase + OFF_STAGE + buf * STAGE_BYTES + A_BYTES;
        #pragma unroll
        for (int i = 0; i < 8; i++)
            cp16(bbase + dstoB[i], ws + (size_t)(i * 32) * GIN);
    };

    // A loader: LDG fp32 (sector-perfect: 4 rows x full 256B row per 2 instrs)
    // thread covers rows lrr+32i, fp32 cols [lss*8 .. lss*8+8)
    uint32_t astso[4];
    #pragma unroll
    for (int i = 0; i < 4; i++)
        astso[i] = swz((uint32_t)((lrr + i * 32) * 128 + lss * 16));

    float4 ldgbuf[8];                // 4 rows x 2 float4

    auto ldgA = [&](int q) {
        const int t    = q >> 2;
        const int kc   = q & 3;
        const int tile = bid + t * NCTA;
        const int g    = tile >> 6;
        const int mt   = tile & 63;
        const float* base = x + (size_t)(mt * MT + lrr) * INF
                              + g * GIN + kc * KCH + lss * 8;
        #pragma unroll
        for (int i = 0; i < 4; i++) {
            const float4* p = (const float4*)(base + (size_t)(i * 32) * INF);
            ldgbuf[2 * i]     = p[0];
            ldgbuf[2 * i + 1] = p[1];
        }
    };

    auto stsA = [&](int buf) {
        const uint32_t ab = sbase + OFF_STAGE + buf * STAGE_BYTES;
        #pragma unroll
        for (int i = 0; i < 4; i++) {
            uint32_t h0 = h2u(__floats2half2_rn(ldgbuf[2*i].x,   ldgbuf[2*i].y));
            uint32_t h1 = h2u(__floats2half2_rn(ldgbuf[2*i].z,   ldgbuf[2*i].w));
            uint32_t h2 = h2u(__floats2half2_rn(ldgbuf[2*i+1].x, ldgbuf[2*i+1].y));
            uint32_t h3 = h2u(__floats2half2_rn(ldgbuf[2*i+1].z, ldgbuf[2*i+1].w));
            asm volatile("st.shared.v4.b32 [%0], {%1,%2,%3,%4};"
                         :: "r"(ab + astso[i]), "r"(h0), "r"(h1), "r"(h2), "r"(h3)
                         : "memory");
        }
    };

    // tiles for this CTA: bid, bid+NCTA, ...
    const int ntiles = (TILES - 1 - bid) / NCTA + 1;
    const int qtot = ntiles * NCHUNK;

    // ---- prologue ----
    ldgA(0);
    stsA(0);
    loadB(0, 0); asm volatile("cp.async.commit_group;" ::: "memory");
    ldgA(1);
    loadB(1, 1); asm volatile("cp.async.commit_group;" ::: "memory");

    // ---- per-warp geometry: 2(M) x 4(N) warps, warp tile 64x64 ----
    const int wid  = tid >> 5;
    const int lane = tid & 31;
    const int wm = wid >> 2;          // 0..1
    const int wn = wid & 3;           // 0..3
    const int grp = lane >> 2;        // 0..7
    const int tig = lane & 3;         // 0..3
    const int kk0 = wid & 3;          // stagger k-step order per warp

    // ldmatrix lane geometry (b16, canonical m16n8k16 fragments)
    const int q8 = lane >> 3;         // 0..3
    const int i8 = lane & 7;          // 0..7
    const uint32_t ix = (uint32_t)i8 << 4;
    const uint32_t aq16 = (uint32_t)((q8 >> 1) << 4);
    const uint32_t arow = (uint32_t)(((q8 & 1) * 8 + i8) * 128) + (uint32_t)(wm << 13);
    const uint32_t bq16 = (uint32_t)((q8 & 1) << 4);
    const uint32_t brow = (uint32_t)(((q8 >> 1) * 8 + i8) * 128) + (uint32_t)(wn << 13);

    float acc[4][8][4];               // [m16-tile][n8-tile][reg] = 128 regs
    #pragma unroll
    for (int a = 0; a < 4; a++)
        #pragma unroll
        for (int b = 0; b < 8; b++)
            #pragma unroll
            for (int c = 0; c < 4; c++) acc[a][b][c] = 0.f;

    // ---- flat persistent mainloop over (tile, k64-chunk) ----
    int buf = 0;                      // q % 3
    #pragma unroll 1
    for (int q = 0; q < qtot; q++) {
        asm volatile("cp.async.wait_group 1;" ::: "memory");
        __syncthreads();   // stage q (A STS + B cp.async) visible

        if (q + 1 < qtot) stsA((buf == 2) ? 0 : buf + 1);
        if (q + 2 < qtot) {
            ldgA(q + 2);
            loadB(q + 2, (buf == 0) ? 2 : buf - 1);
            asm volatile("cp.async.commit_group;" ::: "memory");
        } else {
            asm volatile("cp.async.commit_group;" ::: "memory"); // uniform count
        }

        const uint32_t stage = sbase + OFF_STAGE + buf * STAGE_BYTES;
        const uint32_t Arow = stage + arow;
        const uint32_t Brow = stage + A_BYTES + brow;

        #pragma unroll
        for (int j = 0; j < 4; j++) {
            const int kk = (j + kk0) & 3;           // k16 step within k64 row
            const uint32_t cxA = ((uint32_t)(kk * 32) + aq16) ^ ix;
            const uint32_t cxB = ((uint32_t)(kk * 32) + bq16) ^ ix;

            uint32_t af[4][4];
            #pragma unroll
            for (int mti = 0; mti < 4; mti++)
                ldsm4(af[mti][0], af[mti][1], af[mti][2], af[mti][3],
                      Arow + (uint32_t)(mti * 2048) + cxA);

            uint32_t bf[8][2];
            #pragma unroll
            for (int nt2 = 0; nt2 < 4; nt2++)
                ldsm4(bf[2 * nt2][0], bf[2 * nt2][1],
                      bf[2 * nt2 + 1][0], bf[2 * nt2 + 1][1],
                      Brow + (uint32_t)(nt2 * 2048) + cxB);

            #pragma unroll
            for (int mti = 0; mti < 4; mti++)
                #pragma unroll
                for (int nti = 0; nti < 8; nti++)
                    mma_f16(acc[mti][nti],
                            af[mti][0], af[mti][1], af[mti][2], af[mti][3],
                            bf[nti][0], bf[nti][1]);
        }

        // ---- tile boundary: smem-staged coalesced epilogue ----
        if ((q & 3) == 3) {
            const int tile = bid + (q >> 2) * NCTA;
            const int g    = tile >> 6;
            const int m0   = (tile & 63) * MT;
            const int gb   = g * GOUT;

            const float* bp = bias + gb + wn * 64 + tig * 2;
            float2 bv[8];
            #pragma unroll
            for (int nti = 0; nti < 8; nti++)
                bv[nti] = *(const float2*)(bp + nti * 8);

            const uint32_t epi = sbase + OFF_EPI;
            const uint32_t scol = (uint32_t)((wn * 64 + tig * 2) * 4);

            #pragma unroll
            for (int p = 0; p < 2; p++) {
                // stage 64 rows (mti pair 2p, 2p+1) with bias added
                #pragma unroll
                for (int mloc = 0; mloc < 2; mloc++) {
                    const int mti = 2 * p + mloc;
                    const uint32_t a0 = epi
                        + (uint32_t)((wm * 32 + mloc * 16 + grp) * EPI_STRIDE_B)
                        + scol;
                    const uint32_t a1 = a0 + 8u * EPI_STRIDE_B;
                    #pragma unroll
                    for (int nti = 0; nti < 8; nti++) {
                        float v0x = acc[mti][nti][0] + bv[nti].x;
                        float v0y = acc[mti][nti][1] + bv[nti].y;
                        float v1x = acc[mti][nti][2] + bv[nti].x;
                        float v1y = acc[mti][nti][3] + bv[nti].y;
                        asm volatile("st.shared.v2.f32 [%0], {%1,%2};"
                                     :: "r"(a0 + nti * 32), "f"(v0x), "f"(v0y)
                                     : "memory");
                        asm volatile("st.shared.v2.f32 [%0], {%1,%2};"
                                     :: "r"(a1 + nti * 32), "f"(v1x), "f"(v1y)
                                     : "memory");
                        acc[mti][nti][0] = 0.f; acc[mti][nti][1] = 0.f;
                        acc[mti][nti][2] = 0.f; acc[mti][nti][3] = 0.f;
                    }
                }
                __syncthreads();
                // coalesced flush: 4 rows x 128B per warp instr
                #pragma unroll
                for (int jj = 0; jj < 2; jj++) {
                    const int lr = (tid >> 3) + 32 * jj;
                    const int grow = m0 + ((lr >> 5) << 6)
                                   + (2 * p + ((lr >> 4) & 1)) * 16 + (lr & 15);
                    float* yr = y + (size_t)grow * INF + gb + (tid & 7) * 4;
                    const uint32_t rb = epi + (uint32_t)(lr * EPI_STRIDE_B)
                                      + (uint32_t)((tid & 7) * 16);
                    #pragma unroll
                    for (int i = 0; i < 8; i++) {
                        float vx, vy, vz, vw;
                        asm volatile("ld.shared.v4.f32 {%0,%1,%2,%3}, [%4];"
                                     : "=f"(vx), "=f"(vy), "=f"(vz), "=f"(vw)
                                     : "r"(rb + i * 128));
                        float4 v; v.x = vx; v.y = vy; v.z = vz; v.w = vw;
                        *(float4*)(yr + i * 32) = v;
                    }
                }
                __syncthreads();
            }
        }

        buf = (buf == 2) ? 0 : buf + 1;
    }
}

extern "C" void kernel_launch(void* const* d_in, const int* in_sizes, int n_in,
                              void* d_out, int out_size) {
    const float* x  = (const float*)d_in[0];
    const float* Wt = (const float*)d_in[1];
    const float* b  = (const float*)d_in[2];
    float* y = (float*)d_out;

    cudaFuncSetAttribute(GroupedLinear_35364760715975_kernel,
                         cudaFuncAttributeMaxDynamicSharedMemorySize, SMEM_TOTAL);

    // 1) convert W (1M f32) to fp16 rne (~1us)
    __half* wh_dev = nullptr;
    cudaGetSymbolAddress((void**)&wh_dev, g_Wh);
    GroupedLinear_cvtW_kernel<<<256, 256>>>((const float4*)Wt,
                                            (uint2*)wh_dev, NG * GOUT * GIN / 4);

    // 2) persistent fused cvt+GEMM: 152 CTAs (1 per SM on GB300)
    GroupedLinear_35364760715975_kernel<<<NCTA, NTHREADS, SMEM_TOTAL>>>(x, b, y);
}

// round 13
// speedup vs baseline: 1.3012x; 1.3012x over previous
#include <cuda_runtime.h>
#include <cuda_fp16.h>
#include <cstdint>

// ---------------------------------------------------------------------------
// GroupedLinear: y[b, g*256+o] = sum_i x[b, g*256+i] * W[g,o,i] + bias[g,o]
// 16 independent GEMMs: M=8192, N=256, K=256, fp32 in/out.
//
// R11 (82.4us): fused cvt GEMM, scattered epilogue, sector-wasteful A-LDG.
// R12 (94.3us): staged epilogue regressed (serialized barriers at 1 CTA/SM).
// R13: strict A/B = R11 base + ONLY sector-perfect A-LDG (4 rows x 32B
// contiguous per thread, 2x LDG.128 per row). Epilogue back to R11's
// barrier-free form. Persistent 152 CTAs, 3-stage, mma.m16n8k16.f16.
// ---------------------------------------------------------------------------

namespace gl {

constexpr int INF  = 4096;
constexpr int NG   = 16;
constexpr int GIN  = 256;          // K per group
constexpr int GOUT = 256;          // N per group
constexpr int MT   = 128;          // CTA M tile
constexpr int NT   = 256;          // CTA N tile (full group)
constexpr int KCH  = 64;           // K chunk: 64 halves = 128 B rows
constexpr int NCHUNK = 4;          // K chunks per tile (256/64)
constexpr int TILES = 1024;        // 16 groups x 64 m-tiles
constexpr int NCTA  = 152;         // 1 CTA per SM (GB300: 152 SMs)
constexpr int NTHREADS = 256;      // 8 warps, 2(M) x 4(N), warp tile 64x64

constexpr int A_BYTES = MT * KCH * 2;           // 16 KB per stage
constexpr int B_BYTES = NT * KCH * 2;           // 32 KB per stage
constexpr int STAGE_BYTES = A_BYTES + B_BYTES;  // 48 KB

constexpr int OFF_STAGE = 1024;
constexpr int SMEM_TOTAL = OFF_STAGE + 3 * STAGE_BYTES;  // 148480 B -> 1 CTA/SM

__device__ __forceinline__ uint32_t swz(uint32_t x) {
    return x ^ ((x >> 3) & 0x70);
}

__device__ __forceinline__ void cp16(uint32_t dst, const void* src) {
    asm volatile("cp.async.cg.shared.global [%0], [%1], 16;"
                 :: "r"(dst), "l"(src) : "memory");
}

__device__ __forceinline__ uint32_t smem_u32(const void* p) {
    uint32_t a;
    asm("{ .reg .u64 t; cvta.to.shared.u64 t, %1; cvt.u32.u64 %0, t; }"
        : "=r"(a) : "l"(p));
    return a;
}

__device__ __forceinline__ void ldsm4(uint32_t& r0, uint32_t& r1,
                                      uint32_t& r2, uint32_t& r3,
                                      uint32_t addr) {
    asm volatile("ldmatrix.sync.aligned.m8n8.x4.shared.b16 {%0,%1,%2,%3}, [%4];"
                 : "=r"(r0), "=r"(r1), "=r"(r2), "=r"(r3) : "r"(addr));
}

__device__ __forceinline__ void mma_f16(float* c,
                                        uint32_t a0, uint32_t a1,
                                        uint32_t a2, uint32_t a3,
                                        uint32_t b0, uint32_t b1) {
    asm volatile(
        "mma.sync.aligned.m16n8k16.row.col.f32.f16.f16.f32 "
        "{%0,%1,%2,%3}, {%4,%5,%6,%7}, {%8,%9}, {%0,%1,%2,%3};"
        : "+f"(c[0]), "+f"(c[1]), "+f"(c[2]), "+f"(c[3])
        : "r"(a0), "r"(a1), "r"(a2), "r"(a3), "r"(b0), "r"(b1));
}

__device__ __forceinline__ uint32_t h2u(__half2 h) {
    return *reinterpret_cast<uint32_t*>(&h);
}

} // namespace gl

using namespace gl;

// fp16 copy of W (2MB), produced once per launch (idempotent, deterministic).
__device__ __half g_Wh[NG * GOUT * GIN];

__global__ __launch_bounds__(256, 8)
void GroupedLinear_cvtW_kernel(const float4* __restrict__ in,
                               uint2* __restrict__ out, int n4) {
    const int stride = gridDim.x * 256;
    for (int i = blockIdx.x * 256 + threadIdx.x; i < n4; i += stride) {
        float4 v = in[i];
        __half2 lo = __floats2half2_rn(v.x, v.y);
        __half2 hi = __floats2half2_rn(v.z, v.w);
        uint2 o;
        o.x = *reinterpret_cast<uint32_t*>(&lo);
        o.y = *reinterpret_cast<uint32_t*>(&hi);
        out[i] = o;
    }
}

__global__ __launch_bounds__(NTHREADS, 1)
void GroupedLinear_35364760715975_kernel(const float* __restrict__ x,
                                         const float* __restrict__ bias,
                                         float* __restrict__ y)
{
    extern __shared__ char smem[];
    const uint32_t sbase = smem_u32(smem);
    const int tid = threadIdx.x;
    const int bid = blockIdx.x;

    // ---- shared loader lane geometry: 4 rows x 128B per warp instr ----
    const int lrr = tid >> 3;        // row 0..31
    const int lss = tid & 7;         // 16B slot within 128B fp16 row

    // B loader (cp.async from g_Wh): 8 iters x 32 rows = 256 rows
    uint32_t dstoB[8];
    #pragma unroll
    for (int i = 0; i < 8; i++)
        dstoB[i] = swz((uint32_t)((lrr + i * 32) * 128 + lss * 16));

    auto loadB = [&](int q, int buf) {
        const int t  = q >> 2;
        const int kc = q & 3;
        const int g  = (bid + t * NCTA) >> 6;
        const __half* ws = g_Wh + (size_t)g * GOUT * GIN
                                + (size_t)lrr * GIN + kc * KCH + lss * 8;
        const uint32_t bbase = sbase + OFF_STAGE + buf * STAGE_BYTES + A_BYTES;
        #pragma unroll
        for (int i = 0; i < 8; i++)
            cp16(bbase + dstoB[i], ws + (size_t)(i * 32) * GIN);
    };

    // A loader: sector-perfect LDG fp32 -> cvt(rne) -> STS.128 fp16.
    // Thread covers rows lrr+32i, fp32 cols [lss*8 .. lss*8+8) = 32B contiguous.
    uint32_t astso[4];
    #pragma unroll
    for (int i = 0; i < 4; i++)
        astso[i] = swz((uint32_t)((lrr + i * 32) * 128 + lss * 16));

    float4 ldgbuf[8];                // 4 rows x 2 float4

    auto ldgA = [&](int q) {
        const int t    = q >> 2;
        const int kc   = q & 3;
        const int tile = bid + t * NCTA;
        const int g    = tile >> 6;
        const int mt   = tile & 63;
        const float* base = x + (size_t)(mt * MT + lrr) * INF
                              + g * GIN + kc * KCH + lss * 8;
        #pragma unroll
        for (int i = 0; i < 4; i++) {
            const float4* p = (const float4*)(base + (size_t)(i * 32) * INF);
            ldgbuf[2 * i]     = p[0];
            ldgbuf[2 * i + 1] = p[1];
        }
    };

    auto stsA = [&](int buf) {
        const uint32_t ab = sbase + OFF_STAGE + buf * STAGE_BYTES;
        #pragma unroll
        for (int i = 0; i < 4; i++) {
            uint32_t h0 = h2u(__floats2half2_rn(ldgbuf[2*i].x,   ldgbuf[2*i].y));
            uint32_t h1 = h2u(__floats2half2_rn(ldgbuf[2*i].z,   ldgbuf[2*i].w));
            uint32_t h2 = h2u(__floats2half2_rn(ldgbuf[2*i+1].x, ldgbuf[2*i+1].y));
            uint32_t h3 = h2u(__floats2half2_rn(ldgbuf[2*i+1].z, ldgbuf[2*i+1].w));
            asm volatile("st.shared.v4.b32 [%0], {%1,%2,%3,%4};"
                         :: "r"(ab + astso[i]), "r"(h0), "r"(h1), "r"(h2), "r"(h3)
                         : "memory");
        }
    };

    // tiles for this CTA: bid, bid+NCTA, ...
    const int ntiles = (TILES - 1 - bid) / NCTA + 1;
    const int qtot = ntiles * NCHUNK;

    // ---- prologue ----
    ldgA(0);
    stsA(0);
    loadB(0, 0); asm volatile("cp.async.commit_group;" ::: "memory");
    ldgA(1);
    loadB(1, 1); asm volatile("cp.async.commit_group;" ::: "memory");

    // ---- per-warp geometry: 2(M) x 4(N) warps, warp tile 64x64 ----
    const int wid  = tid >> 5;
    const int lane = tid & 31;
    const int wm = wid >> 2;          // 0..1
    const int wn = wid & 3;           // 0..3
    const int grp = lane >> 2;        // 0..7
    const int tig = lane & 3;         // 0..3
    const int kk0 = wid & 3;          // stagger k-step order per warp

    // ldmatrix lane geometry (b16, canonical m16n8k16 fragments)
    const int q8 = lane >> 3;         // 0..3
    const int i8 = lane & 7;          // 0..7
    const uint32_t ix = (uint32_t)i8 << 4;
    const uint32_t aq16 = (uint32_t)((q8 >> 1) << 4);
    const uint32_t arow = (uint32_t)(((q8 & 1) * 8 + i8) * 128) + (uint32_t)(wm << 13);
    const uint32_t bq16 = (uint32_t)((q8 & 1) << 4);
    const uint32_t brow = (uint32_t)(((q8 >> 1) * 8 + i8) * 128) + (uint32_t)(wn << 13);

    float acc[4][8][4];               // [m16-tile][n8-tile][reg] = 128 regs
    #pragma unroll
    for (int a = 0; a < 4; a++)
        #pragma unroll
        for (int b = 0; b < 8; b++)
            #pragma unroll
            for (int c = 0; c < 4; c++) acc[a][b][c] = 0.f;

    // ---- flat persistent mainloop over (tile, k64-chunk) ----
    int buf = 0;                      // q % 3
    #pragma unroll 1
    for (int q = 0; q < qtot; q++) {
        asm volatile("cp.async.wait_group 1;" ::: "memory");
        __syncthreads();   // stage q (A STS + B cp.async) visible

        if (q + 1 < qtot) stsA((buf == 2) ? 0 : buf + 1);
        if (q + 2 < qtot) {
            ldgA(q + 2);
            loadB(q + 2, (buf == 0) ? 2 : buf - 1);
            asm volatile("cp.async.commit_group;" ::: "memory");
        } else {
            asm volatile("cp.async.commit_group;" ::: "memory"); // uniform count
        }

        const uint32_t stage = sbase + OFF_STAGE + buf * STAGE_BYTES;
        const uint32_t Arow = stage + arow;
        const uint32_t Brow = stage + A_BYTES + brow;

        #pragma unroll
        for (int j = 0; j < 4; j++) {
            const int kk = (j + kk0) & 3;           // k16 step within k64 row
            const uint32_t cxA = ((uint32_t)(kk * 32) + aq16) ^ ix;
            const uint32_t cxB = ((uint32_t)(kk * 32) + bq16) ^ ix;

            uint32_t af[4][4];
            #pragma unroll
            for (int mti = 0; mti < 4; mti++)
                ldsm4(af[mti][0], af[mti][1], af[mti][2], af[mti][3],
                      Arow + (uint32_t)(mti * 2048) + cxA);

            uint32_t bf[8][2];
            #pragma unroll
            for (int nt2 = 0; nt2 < 4; nt2++)
                ldsm4(bf[2 * nt2][0], bf[2 * nt2][1],
                      bf[2 * nt2 + 1][0], bf[2 * nt2 + 1][1],
                      Brow + (uint32_t)(nt2 * 2048) + cxB);

            #pragma unroll
            for (int mti = 0; mti < 4; mti++)
                #pragma unroll
                for (int nti = 0; nti < 8; nti++)
                    mma_f16(acc[mti][nti],
                            af[mti][0], af[mti][1], af[mti][2], af[mti][3],
                            bf[nti][0], bf[nti][1]);
        }

        // ---- tile boundary: barrier-free inline epilogue (R11 form) ----
        if ((q & 3) == 3) {
            const int tile = bid + (q >> 2) * NCTA;
            const int g    = tile >> 6;
            const int m0   = (tile & 63) * MT;
            const int gb   = g * GOUT;

            const float* bp = bias + gb + wn * 64 + tig * 2;
            float2 bv[8];
            #pragma unroll
            for (int nti = 0; nti < 8; nti++)
                bv[nti] = *(const float2*)(bp + nti * 8);

            #pragma unroll
            for (int mti = 0; mti < 4; mti++) {
                const int row0 = m0 + wm * 64 + mti * 16 + grp;
                float* yr0 = y + (size_t)row0 * INF + gb + wn * 64 + tig * 2;
                float* yr1 = yr0 + (size_t)8 * INF;
                #pragma unroll
                for (int nti = 0; nti < 8; nti++) {
                    float2 v0, v1;
                    v0.x = acc[mti][nti][0] + bv[nti].x;
                    v0.y = acc[mti][nti][1] + bv[nti].y;
                    v1.x = acc[mti][nti][2] + bv[nti].x;
                    v1.y = acc[mti][nti][3] + bv[nti].y;
                    *(float2*)(yr0 + nti * 8) = v0;
                    *(float2*)(yr1 + nti * 8) = v1;
                    acc[mti][nti][0] = 0.f; acc[mti][nti][1] = 0.f;
                    acc[mti][nti][2] = 0.f; acc[mti][nti][3] = 0.f;
                }
            }
        }

        buf = (buf == 2) ? 0 : buf + 1;
    }
}

extern "C" void kernel_launch(void* const* d_in, const int* in_sizes, int n_in,
                              void* d_out, int out_size) {
    const float* x  = (const float*)d_in[0];
    const float* Wt = (const float*)d_in[1];
    const float* b  = (const float*)d_in[2];
    float* y = (float*)d_out;

    cudaFuncSetAttribute(GroupedLinear_35364760715975_kernel,
                         cudaFuncAttributeMaxDynamicSharedMemorySize, SMEM_TOTAL);

    // 1) convert W (1M f32) to fp16 rne (~1us)
    __half* wh_dev = nullptr;
    cudaGetSymbolAddress((void**)&wh_dev, g_Wh);
    GroupedLinear_cvtW_kernel<<<256, 256>>>((const float4*)Wt,
                                            (uint2*)wh_dev, NG * GOUT * GIN / 4);

    // 2) persistent fused cvt+GEMM: 152 CTAs (1 per SM on GB300)
    GroupedLinear_35364760715975_kernel<<<NCTA, NTHREADS, SMEM_TOTAL>>>(x, b, y);
}